// round 12
// baseline (speedup 1.0000x reference)
#include <cuda_runtime.h>

static constexpr int BB = 2, CC = 64, HH = 256, WW = 256;
static constexpr int HPAD = 258, WPAD = 258;
static constexpr int NPIX = BB * HH * WW;

// Scratch (device globals; no allocation in kernel_launch)
__device__ float g_xp[BB * HPAD * WPAD * CC];   // NHWC zero-padded x  (~34 MB)
__device__ float g_off[36 * NPIX];              // planar offsets: plane p in [0,36), pixel-major
__device__ float g_W[27 * 64 * 64];             // folded weights [t][c][o]; t = branch*9 + n
__device__ float g_Wp[9 * 64 * 48];             // offset-conv weights [n][c][48] (4 groups of 12, 9 used)
__device__ float g_bias[64];

// ---------------- f32x2 helpers (Blackwell packed fp32 FMA) ----------------
__device__ __forceinline__ unsigned long long dup2(float w) {
    unsigned long long r;
    asm("mov.b64 %0, {%1, %1};" : "=l"(r) : "f"(w));
    return r;
}
__device__ __forceinline__ void ffma2(unsigned long long& d, unsigned long long a, unsigned long long b) {
    asm("fma.rn.f32x2 %0, %1, %2, %0;" : "+l"(d) : "l"(a), "l"(b));
}
__device__ __forceinline__ float lo32(unsigned long long v) { return __uint_as_float((unsigned int)v); }
__device__ __forceinline__ float hi32(unsigned long long v) { return __uint_as_float((unsigned int)(v >> 32)); }

// ---------------- consolidated prep: border-zero + weight folds + bias ----------------
static constexpr int PREP_NB = BB * 1028 * 16;     // 32896
static constexpr int PREP_NW = 27 * 64 * 64;       // 110592
static constexpr int PREP_NP = 9 * 64 * 48;        // 27648
static constexpr int PREP_TOTAL = PREP_NB + PREP_NW + PREP_NP + 64;

__global__ void __launch_bounds__(256) k_prep(
        const float* __restrict__ wo, const float* __restrict__ wcx,
        const float* __restrict__ wm, const float* __restrict__ wcy,
        const float* __restrict__ wpx, const float* __restrict__ wpy,
        const float* __restrict__ bo, const float* __restrict__ bm) {
    int gi = blockIdx.x * 256 + threadIdx.x;
    if (gi < PREP_NB) {
        // ---- zero ONLY the pad ring (interior is overwritten by k_transpose) ----
        int i = gi;
        int c4 = i & 15;
        int p = (i >> 4) % 1028;
        int b = i / (1028 * 16);
        int h, w;
        if (p < 258)      { h = 0;        w = p; }
        else if (p < 516) { h = 257;      w = p - 258; }
        else if (p < 772) { h = p - 515;  w = 0; }       // h in 1..256
        else              { h = p - 771;  w = 257; }
        reinterpret_cast<float4*>(g_xp + ((b * HPAD + h) * WPAD + w) * CC)[c4] =
            make_float4(0.f, 0.f, 0.f, 0.f);
    } else if (gi < PREP_NB + PREP_NW) {
        // ---- fold wo into branch weights ----
        int idx = gi - PREP_NB;
        int o = idx & 63;
        int c = (idx >> 6) & 63;
        int t = idx >> 12;
        int br = t / 9, n = t - br * 9;
        const float* wsrc = (br == 0) ? wcx : (br == 1 ? wm : wcy);
        int col0 = br * 64;
        float s = 0.f;
#pragma unroll 8
        for (int k = 0; k < 64; k++) s += wo[o * 192 + col0 + k] * wsrc[(k * 64 + c) * 9 + n];
        g_W[(t * 64 + c) * 64 + o] = s;
    } else if (gi < PREP_NB + PREP_NW + PREP_NP) {
        // ---- pack offset-conv weights ----
        int idx = gi - PREP_NB - PREP_NW;
        int j = idx % 48;
        int c = (idx / 48) & 63;
        int n = idx / (48 * 64);
        int jg = j / 12, i = j % 12;
        float v = 0.f;
        if (i < 9) {
            int jj = jg * 9 + i;
            v = (jj < 18) ? wpx[(jj * 64 + c) * 9 + n] : wpy[((jj - 18) * 64 + c) * 9 + n];
        }
        g_Wp[idx] = v;
    } else if (gi < PREP_TOTAL) {
        // ---- fused bias ----
        int o = gi - PREP_NB - PREP_NW - PREP_NP;
        float s = bo[o];
#pragma unroll 8
        for (int k = 0; k < 64; k++) s += wo[o * 192 + 64 + k] * bm[k];
        g_bias[o] = s;
    }
}

// ---------------- NCHW -> padded NHWC transpose ----------------
__global__ void __launch_bounds__(256) k_transpose(const float* __restrict__ x) {
    __shared__ float tile[64][65];
    int bid = blockIdx.x;
    int wt = bid & 3, h = (bid >> 2) & 255, b = bid >> 10;
    int w0 = wt * 64;
    int tid = threadIdx.x;
    int lw = tid & 63, g = tid >> 6;
#pragma unroll
    for (int i = 0; i < 16; i++) {
        int c = g * 16 + i;
        tile[c][lw] = x[((b * CC + c) * HH + h) * WW + w0 + lw];
    }
    __syncthreads();
    int lc = tid & 63;
#pragma unroll
    for (int i = 0; i < 16; i++) {
        int w = g * 16 + i;
        g_xp[((b * HPAD + h + 1) * WPAD + (w0 + w + 1)) * CC + lc] = tile[lc][w];
    }
}

// ---------------- offset conv: 36 planes (both branches), planar output ----------------
// Thread (pxg, jg): pixels [pxg*4, pxg*4+4) as 2 f32x2 pairs, planes [jg*9, jg*9+9)
__global__ void __launch_bounds__(128, 4) k_offsets(const float* __restrict__ bpx,
                                                    const float* __restrict__ bpy) {
    __shared__ float Ssh[64][128];
    __shared__ float Wsh[64][48];
    int bid = blockIdx.x;
    int w0 = (bid & 1) * 128, h = (bid >> 1) & 255, b = bid >> 9;
    int tid = threadIdx.x;
    int pxg = tid & 31, jg = tid >> 5;

    unsigned long long acc[2][9];   // [px-pair][plane], f32x2-packed
#pragma unroll
    for (int i = 0; i < 2; i++)
#pragma unroll
        for (int j = 0; j < 9; j++) acc[i][j] = 0ull;

#pragma unroll 1
    for (int n = 0; n < 9; n++) {
        int kh = n / 3 - 1, kw = n % 3 - 1;
        {
            const float4* wsrc = reinterpret_cast<const float4*>(g_Wp + n * 64 * 48);
            float4* wdst = reinterpret_cast<float4*>(&Wsh[0][0]);
#pragma unroll
            for (int i = 0; i < 6; i++) wdst[i * 128 + tid] = wsrc[i * 128 + tid];
        }
        const float4* src = reinterpret_cast<const float4*>(
            g_xp + ((b * HPAD + h + 1 + kh) * WPAD + (w0 + tid + 1 + kw)) * CC);
#pragma unroll 4
        for (int c4 = 0; c4 < 16; c4++) {
            float4 v = src[c4];
            Ssh[4 * c4 + 0][tid] = v.x;
            Ssh[4 * c4 + 1][tid] = v.y;
            Ssh[4 * c4 + 2][tid] = v.z;
            Ssh[4 * c4 + 3][tid] = v.w;
        }
        __syncthreads();
#pragma unroll 4
        for (int c = 0; c < 64; c++) {
            ulonglong2 sp2 = *reinterpret_cast<const ulonglong2*>(&Ssh[c][pxg * 4]);
            float4 wA = *reinterpret_cast<const float4*>(&Wsh[c][jg * 12]);
            float4 wB = *reinterpret_cast<const float4*>(&Wsh[c][jg * 12 + 4]);
            float4 wC = *reinterpret_cast<const float4*>(&Wsh[c][jg * 12 + 8]);
            float wv[9] = {wA.x, wA.y, wA.z, wA.w, wB.x, wB.y, wB.z, wB.w, wC.x};
            unsigned long long sp[2] = {sp2.x, sp2.y};
#pragma unroll
            for (int j = 0; j < 9; j++) {
                unsigned long long wd = dup2(wv[j]);
                ffma2(acc[0][j], sp[0], wd);
                ffma2(acc[1][j], sp[1], wd);
            }
        }
        __syncthreads();
    }
    // planar store: plane = jg*9 + j, pixel-major within the plane (coalesced)
#pragma unroll
    for (int j = 0; j < 9; j++) {
        int jj = jg * 9 + j;
        float bp = (jj < 18) ? bpx[jj] : bpy[jj - 18];
        int pixbase = (b * HH + h) * WW + w0 + pxg * 4;
        g_off[(size_t)jj * NPIX + pixbase + 0] = lo32(acc[0][j]) + bp;
        g_off[(size_t)jj * NPIX + pixbase + 1] = hi32(acc[0][j]) + bp;
        g_off[(size_t)jj * NPIX + pixbase + 2] = lo32(acc[1][j]) + bp;
        g_off[(size_t)jj * NPIX + pixbase + 3] = hi32(acc[1][j]) + bp;
    }
}

// ---------------- main fused kernel: 27-tap contraction + bias + residual ----------------
// Thread (ox, py) owns pixels [py*8, py*8+8) and output channels
// {ox*4..ox*4+3} ∪ {32+ox*4..32+ox*4+3}  (split mapping -> conflict-free Wsh reads)
__device__ __forceinline__ void km_load_W(int t, float (*Wsh)[64], int tid) {
    const float4* wsrc = reinterpret_cast<const float4*>(g_W + t * 4096);
    float4* wdst = reinterpret_cast<float4*>(&Wsh[0][0]);
#pragma unroll
    for (int i = 0; i < 8; i++) wdst[i * 128 + tid] = wsrc[i * 128 + tid];
}

__device__ __forceinline__ void km_mma(const float (*Ssh)[128], const float (*Wsh)[64],
                                       unsigned long long (*acc)[8], int py, int ox) {
#pragma unroll 8
    for (int c = 0; c < 64; c++) {
        ulonglong2 sa = *reinterpret_cast<const ulonglong2*>(&Ssh[c][py * 8]);
        ulonglong2 sb = *reinterpret_cast<const ulonglong2*>(&Ssh[c][py * 8 + 4]);
        float4 wa = *reinterpret_cast<const float4*>(&Wsh[c][ox * 4]);
        float4 wb = *reinterpret_cast<const float4*>(&Wsh[c][32 + ox * 4]);
        unsigned long long sp[4] = {sa.x, sa.y, sb.x, sb.y};
        unsigned long long wd[8] = {dup2(wa.x), dup2(wa.y), dup2(wa.z), dup2(wa.w),
                                    dup2(wb.x), dup2(wb.y), dup2(wb.z), dup2(wb.w)};
#pragma unroll
        for (int ip = 0; ip < 4; ip++)
#pragma unroll
            for (int j = 0; j < 8; j++) ffma2(acc[ip][j], sp[ip], wd[j]);
    }
}

__global__ void __launch_bounds__(128, 4) k_main(const float* __restrict__ x, float* __restrict__ out) {
    __shared__ float Ssh[64][128];   // S[c][px]
    __shared__ float Wsh[64][64];    // W[c][oc]
    int bid = blockIdx.x;
    int w0 = (bid & 1) * 128, h = (bid >> 1) & 255, b = bid >> 9;
    int tid = threadIdx.x;
    int ox = tid & 7;    // oc group
    int py = tid >> 3;   // px group (8 px)
    int pixw = w0 + tid;
    int pix = (b * HH + h) * WW + pixw;   // this thread's pixel (for offset planes)

    unsigned long long acc[4][8];    // [px-pair][oc-slot], f32x2-packed
#pragma unroll
    for (int i = 0; i < 4; i++)
#pragma unroll
        for (int j = 0; j < 8; j++) acc[i][j] = 0ull;

    // ---------- plain-conv branch: taps t = 9..17, simple shifted copy ----------
#pragma unroll 1
    for (int n = 0; n < 9; n++) {
        int kh = n / 3 - 1, kw = n % 3 - 1;
        km_load_W(9 + n, Wsh, tid);
        const float4* src = reinterpret_cast<const float4*>(
            g_xp + ((b * HPAD + h + 1 + kh) * WPAD + (pixw + 1 + kw)) * CC);
#pragma unroll 4
        for (int c4 = 0; c4 < 16; c4++) {
            float4 v = src[c4];
            Ssh[4 * c4 + 0][tid] = v.x;
            Ssh[4 * c4 + 1][tid] = v.y;
            Ssh[4 * c4 + 2][tid] = v.z;
            Ssh[4 * c4 + 3][tid] = v.w;
        }
        __syncthreads();
        km_mma(Ssh, Wsh, acc, py, ox);
        __syncthreads();
    }

    // ---------- deform branches: (ob=0, t=0..8) and (ob=18, t=18..26) ----------
#pragma unroll 1
    for (int half = 0; half < 2; half++) {
        int ob = half * 18;          // offset-plane base; also the weight-tile base
#pragma unroll 1
        for (int n = 0; n < 9; n++) {
            int kh = n / 3 - 1, kw = n % 3 - 1;

            // issue offset-plane loads FIRST so they overlap the weight-tile load latency
            float offx = g_off[(size_t)(ob + n) * NPIX + pix];
            float offy = g_off[(size_t)(ob + 9 + n) * NPIX + pix];

            km_load_W(ob + n, Wsh, tid);

            float pxf = offx + (float)(h + 1 + kh);
            float pyf = offy + (float)(pixw + 1 + kw);
            float fx = floorf(pxf), fy = floorf(pyf);
            float qltx = fminf(fmaxf(fx, 0.f), 257.f);
            float qlty = fminf(fmaxf(fy, 0.f), 257.f);
            float qrbx = fminf(fmaxf(fx + 1.f, 0.f), 257.f);
            float qrby = fminf(fmaxf(fy + 1.f, 0.f), 257.f);
            float pxc = fminf(fmaxf(pxf, 0.f), 257.f);
            float pyc = fminf(fmaxf(pyf, 0.f), 257.f);
            float gxl = 1.f + (qltx - pxc), gyl = 1.f + (qlty - pyc);
            float gxr = 1.f - (qrbx - pxc), gyr = 1.f - (qrby - pyc);
            float glt = gxl * gyl, grb = gxr * gyr, glb = gxl * gyr, grt = gxr * gyl;
            int ilx = (int)qltx, ily = (int)qlty, irx = (int)qrbx, iry = (int)qrby;
            const float4* pA = reinterpret_cast<const float4*>(g_xp + ((b * HPAD + ilx) * WPAD + ily) * CC);
            const float4* pB = reinterpret_cast<const float4*>(g_xp + ((b * HPAD + irx) * WPAD + iry) * CC);
            const float4* pC = reinterpret_cast<const float4*>(g_xp + ((b * HPAD + ilx) * WPAD + iry) * CC);
            const float4* pD = reinterpret_cast<const float4*>(g_xp + ((b * HPAD + irx) * WPAD + ily) * CC);
#pragma unroll 4
            for (int c4 = 0; c4 < 16; c4++) {
                float4 a = pA[c4], bb = pB[c4], cv = pC[c4], dv = pD[c4];
                float4 v;
                v.x = glt * a.x + grb * bb.x + glb * cv.x + grt * dv.x;
                v.y = glt * a.y + grb * bb.y + glb * cv.y + grt * dv.y;
                v.z = glt * a.z + grb * bb.z + glb * cv.z + grt * dv.z;
                v.w = glt * a.w + grb * bb.w + glb * cv.w + grt * dv.w;
                Ssh[4 * c4 + 0][tid] = v.x;
                Ssh[4 * c4 + 1][tid] = v.y;
                Ssh[4 * c4 + 2][tid] = v.z;
                Ssh[4 * c4 + 3][tid] = v.w;
            }
            __syncthreads();
            km_mma(Ssh, Wsh, acc, py, ox);
            __syncthreads();
        }
    }

    // epilogue: bias + residual, NCHW output (oc-slot j -> channel per split mapping)
    int pxb = py * 8;
#pragma unroll
    for (int j = 0; j < 8; j++) {
        int oc = (j < 4) ? (ox * 4 + j) : (32 + ox * 4 + (j - 4));
        float bsum = g_bias[oc];
        size_t base = ((size_t)((b * CC + oc) * HH + h)) * WW + w0 + pxb;
        float4 r0 = *reinterpret_cast<const float4*>(&x[base]);
        float4 r1 = *reinterpret_cast<const float4*>(&x[base + 4]);
        float4 o0, o1;
        o0.x = lo32(acc[0][j]) + bsum + r0.x;
        o0.y = hi32(acc[0][j]) + bsum + r0.y;
        o0.z = lo32(acc[1][j]) + bsum + r0.z;
        o0.w = hi32(acc[1][j]) + bsum + r0.w;
        o1.x = lo32(acc[2][j]) + bsum + r1.x;
        o1.y = hi32(acc[2][j]) + bsum + r1.y;
        o1.z = lo32(acc[3][j]) + bsum + r1.z;
        o1.w = hi32(acc[3][j]) + bsum + r1.w;
        *reinterpret_cast<float4*>(&out[base]) = o0;
        *reinterpret_cast<float4*>(&out[base + 4]) = o1;
    }
}

extern "C" void kernel_launch(void* const* d_in, const int* in_sizes, int n_in,
                              void* d_out, int out_size) {
    const float* x    = (const float*)d_in[0];
    const float* wp_x = (const float*)d_in[1];
    const float* bp_x = (const float*)d_in[2];
    const float* wc_x = (const float*)d_in[3];
    const float* wm   = (const float*)d_in[4];
    const float* bm   = (const float*)d_in[5];
    const float* wp_y = (const float*)d_in[6];
    const float* bp_y = (const float*)d_in[7];
    const float* wc_y = (const float*)d_in[8];
    const float* wo   = (const float*)d_in[9];
    const float* bo   = (const float*)d_in[10];
    float* out = (float*)d_out;

    k_prep<<<(PREP_TOTAL + 255) / 256, 256>>>(wo, wc_x, wm, wc_y, wp_x, wp_y, bo, bm);
    k_transpose<<<BB * HH * (WW / 64), 256>>>(x);
    k_offsets<<<BB * HH * (WW / 128), 128>>>(bp_x, bp_y);
    k_main<<<BB * HH * (WW / 128), 128>>>(x, out);
}

// round 14
// speedup vs baseline: 2.1329x; 2.1329x over previous
#include <cuda_runtime.h>

static constexpr int BB = 2, CC = 64, HH = 256, WW = 256;
static constexpr int HPAD = 258, WPAD = 258;
static constexpr int NPIX = BB * HH * WW;

// Scratch (device globals; no allocation in kernel_launch)
__device__ float g_xp[BB * HPAD * WPAD * CC];   // NHWC zero-padded x  (~34 MB)
__device__ float g_off[36 * NPIX];              // planar offsets: plane p in [0,36), pixel-major
__device__ float g_W[27 * 64 * 64];             // folded weights [t][c][o]; t = branch*9 + n
__device__ float g_Wp[9 * 64 * 48];             // offset-conv weights [n][c][48]
__device__ float g_bias[64];

// ---------------- f32x2 helpers ----------------
__device__ __forceinline__ unsigned long long dup2(float w) {
    unsigned long long r;
    asm("mov.b64 %0, {%1, %1};" : "=l"(r) : "f"(w));
    return r;
}
__device__ __forceinline__ void ffma2(unsigned long long& d, unsigned long long a, unsigned long long b) {
    asm("fma.rn.f32x2 %0, %1, %2, %0;" : "+l"(d) : "l"(a), "l"(b));
}
__device__ __forceinline__ float lo32(unsigned long long v) { return __uint_as_float((unsigned int)v); }
__device__ __forceinline__ float hi32(unsigned long long v) { return __uint_as_float((unsigned int)(v >> 32)); }

// ---------------- consolidated prep ----------------
static constexpr int PREP_NB = BB * 1028 * 16;
static constexpr int PREP_NW = 27 * 64 * 64;
static constexpr int PREP_NP = 9 * 64 * 48;
static constexpr int PREP_TOTAL = PREP_NB + PREP_NW + PREP_NP + 64;

__global__ void __launch_bounds__(256) k_prep(
        const float* __restrict__ wo, const float* __restrict__ wcx,
        const float* __restrict__ wm, const float* __restrict__ wcy,
        const float* __restrict__ wpx, const float* __restrict__ wpy,
        const float* __restrict__ bo, const float* __restrict__ bm) {
    int gi = blockIdx.x * 256 + threadIdx.x;
    if (gi < PREP_NB) {
        int i = gi;
        int c4 = i & 15;
        int p = (i >> 4) % 1028;
        int b = i / (1028 * 16);
        int h, w;
        if (p < 258)      { h = 0;        w = p; }
        else if (p < 516) { h = 257;      w = p - 258; }
        else if (p < 772) { h = p - 515;  w = 0; }
        else              { h = p - 771;  w = 257; }
        reinterpret_cast<float4*>(g_xp + ((b * HPAD + h) * WPAD + w) * CC)[c4] =
            make_float4(0.f, 0.f, 0.f, 0.f);
    } else if (gi < PREP_NB + PREP_NW) {
        int idx = gi - PREP_NB;
        int o = idx & 63;
        int c = (idx >> 6) & 63;
        int t = idx >> 12;
        int br = t / 9, n = t - br * 9;
        const float* wsrc = (br == 0) ? wcx : (br == 1 ? wm : wcy);
        int col0 = br * 64;
        float s = 0.f;
#pragma unroll 8
        for (int k = 0; k < 64; k++) s += wo[o * 192 + col0 + k] * wsrc[(k * 64 + c) * 9 + n];
        g_W[(t * 64 + c) * 64 + o] = s;
    } else if (gi < PREP_NB + PREP_NW + PREP_NP) {
        int idx = gi - PREP_NB - PREP_NW;
        int j = idx % 48;
        int c = (idx / 48) & 63;
        int n = idx / (48 * 64);
        int jg = j / 12, i = j % 12;
        float v = 0.f;
        if (i < 9) {
            int jj = jg * 9 + i;
            v = (jj < 18) ? wpx[(jj * 64 + c) * 9 + n] : wpy[((jj - 18) * 64 + c) * 9 + n];
        }
        g_Wp[idx] = v;
    } else if (gi < PREP_TOTAL) {
        int o = gi - PREP_NB - PREP_NW - PREP_NP;
        float s = bo[o];
#pragma unroll 8
        for (int k = 0; k < 64; k++) s += wo[o * 192 + 64 + k] * bm[k];
        g_bias[o] = s;
    }
}

// ---------------- NCHW -> padded NHWC transpose ----------------
__global__ void __launch_bounds__(256) k_transpose(const float* __restrict__ x) {
    __shared__ float tile[64][65];
    int bid = blockIdx.x;
    int wt = bid & 3, h = (bid >> 2) & 255, b = bid >> 10;
    int w0 = wt * 64;
    int tid = threadIdx.x;
    int lw = tid & 63, g = tid >> 6;
#pragma unroll
    for (int i = 0; i < 16; i++) {
        int c = g * 16 + i;
        tile[c][lw] = x[((b * CC + c) * HH + h) * WW + w0 + lw];
    }
    __syncthreads();
    int lc = tid & 63;
#pragma unroll
    for (int i = 0; i < 16; i++) {
        int w = g * 16 + i;
        g_xp[((b * HPAD + h + 1) * WPAD + (w0 + w + 1)) * CC + lc] = tile[lc][w];
    }
}

// Cooperative, coalesced fill of Ssh (64ch x 128px) from a contiguous row of pixels.
// Lane mapping: 8 lanes per pixel, each loads channel-quads c4 = lane8, lane8+8.
// Stores use XOR swizzle col' = pp ^ (lane8<<2)  -> conflict-free scalar STS.
__device__ __forceinline__ void fill_plain(float (*Ssh)[128], const float* __restrict__ srow,
                                           int wbase, int sub, int lane8) {
#pragma unroll 1
    for (int g = 0; g < 8; g++) {
        int pp = wbase + g * 4 + sub;
        const float4* src = reinterpret_cast<const float4*>(srow + pp * CC);
        int col = pp ^ (lane8 << 2);
#pragma unroll
        for (int t2 = 0; t2 < 2; t2++) {
            int c4 = lane8 + t2 * 8;
            float4 v = src[c4];
            Ssh[4 * c4 + 0][col] = v.x;
            Ssh[4 * c4 + 1][col] = v.y;
            Ssh[4 * c4 + 2][col] = v.z;
            Ssh[4 * c4 + 3][col] = v.w;
        }
    }
}

// ---------------- offset conv: 36 planes, planar output ----------------
__global__ void __launch_bounds__(128, 4) k_offsets(const float* __restrict__ bpx,
                                                    const float* __restrict__ bpy) {
    __shared__ float Ssh[64][128];
    __shared__ float Wsh[64][48];
    int bid = blockIdx.x;
    int w0 = (bid & 1) * 128, h = (bid >> 1) & 255, b = bid >> 9;
    int tid = threadIdx.x;
    int pxg = tid & 31, jg = tid >> 5;
    int lane = tid & 31, wbase = tid & 96, sub = lane >> 3, lane8 = lane & 7;

    unsigned long long acc[2][9];
#pragma unroll
    for (int i = 0; i < 2; i++)
#pragma unroll
        for (int j = 0; j < 9; j++) acc[i][j] = 0ull;

#pragma unroll 1
    for (int n = 0; n < 9; n++) {
        int kh = n / 3 - 1, kw = n % 3 - 1;
        {
            const float4* wsrc = reinterpret_cast<const float4*>(g_Wp + n * 64 * 48);
            float4* wdst = reinterpret_cast<float4*>(&Wsh[0][0]);
#pragma unroll
            for (int i = 0; i < 6; i++) wdst[i * 128 + tid] = wsrc[i * 128 + tid];
        }
        const float* srow = g_xp + ((b * HPAD + h + 1 + kh) * WPAD + (w0 + 1 + kw)) * CC;
        fill_plain(Ssh, srow, wbase, sub, lane8);
        __syncthreads();
        // contraction with swizzled read: col = (pxg*4) ^ ((c>>2 & 7)<<2)
#pragma unroll 2
        for (int c4r = 0; c4r < 16; c4r++) {
            int col = (pxg * 4) ^ ((c4r & 7) << 2);
#pragma unroll
            for (int comp = 0; comp < 4; comp++) {
                int c = c4r * 4 + comp;
                ulonglong2 sp2 = *reinterpret_cast<const ulonglong2*>(&Ssh[c][col]);
                float4 wA = *reinterpret_cast<const float4*>(&Wsh[c][jg * 12]);
                float4 wB = *reinterpret_cast<const float4*>(&Wsh[c][jg * 12 + 4]);
                float4 wC = *reinterpret_cast<const float4*>(&Wsh[c][jg * 12 + 8]);
                float wv[9] = {wA.x, wA.y, wA.z, wA.w, wB.x, wB.y, wB.z, wB.w, wC.x};
                unsigned long long sp[2] = {sp2.x, sp2.y};
#pragma unroll
                for (int j = 0; j < 9; j++) {
                    unsigned long long wd = dup2(wv[j]);
                    ffma2(acc[0][j], sp[0], wd);
                    ffma2(acc[1][j], sp[1], wd);
                }
            }
        }
        __syncthreads();
    }
#pragma unroll
    for (int j = 0; j < 9; j++) {
        int jj = jg * 9 + j;
        float bp = (jj < 18) ? bpx[jj] : bpy[jj - 18];
        int pixbase = (b * HH + h) * WW + w0 + pxg * 4;
        g_off[(size_t)jj * NPIX + pixbase + 0] = lo32(acc[0][j]) + bp;
        g_off[(size_t)jj * NPIX + pixbase + 1] = hi32(acc[0][j]) + bp;
        g_off[(size_t)jj * NPIX + pixbase + 2] = lo32(acc[1][j]) + bp;
        g_off[(size_t)jj * NPIX + pixbase + 3] = hi32(acc[1][j]) + bp;
    }
}

// ---------------- main fused kernel ----------------
__device__ __forceinline__ void km_load_W(int t, float (*Wsh)[64], int tid) {
    const float4* wsrc = reinterpret_cast<const float4*>(g_W + t * 4096);
    float4* wdst = reinterpret_cast<float4*>(&Wsh[0][0]);
#pragma unroll
    for (int i = 0; i < 8; i++) wdst[i * 128 + tid] = wsrc[i * 128 + tid];
}

// Contraction with swizzled Ssh read.
// addr(i) = (py8 + i) ^ X, X = ((c>>2)&7)<<2  ->  two aligned quads qa/qb (bit-2 flip).
__device__ __forceinline__ void km_mma(const float (*Ssh)[128], const float (*Wsh)[64],
                                       unsigned long long (*acc)[8], int py, int ox) {
    int py8 = py * 8;
#pragma unroll 2
    for (int c4r = 0; c4r < 16; c4r++) {
        int X = (c4r & 7) << 2;
        int colbase = py8 ^ (X & 24);
        int qa = colbase + (X & 4);
        int qb = colbase + ((X & 4) ^ 4);
#pragma unroll
        for (int comp = 0; comp < 4; comp++) {
            int c = c4r * 4 + comp;
            ulonglong2 sa = *reinterpret_cast<const ulonglong2*>(&Ssh[c][qa]);
            ulonglong2 sb = *reinterpret_cast<const ulonglong2*>(&Ssh[c][qb]);
            float4 wa = *reinterpret_cast<const float4*>(&Wsh[c][ox * 4]);
            float4 wb = *reinterpret_cast<const float4*>(&Wsh[c][32 + ox * 4]);
            unsigned long long sp[4] = {sa.x, sa.y, sb.x, sb.y};
            unsigned long long wd[8] = {dup2(wa.x), dup2(wa.y), dup2(wa.z), dup2(wa.w),
                                        dup2(wb.x), dup2(wb.y), dup2(wb.z), dup2(wb.w)};
#pragma unroll
            for (int ip = 0; ip < 4; ip++)
#pragma unroll
                for (int j = 0; j < 8; j++) ffma2(acc[ip][j], sp[ip], wd[j]);
        }
    }
}

__global__ void __launch_bounds__(128, 4) k_main(const float* __restrict__ x, float* __restrict__ out) {
    __shared__ float Ssh[64][128];
    __shared__ float Wsh[64][64];
    int bid = blockIdx.x;
    int w0 = (bid & 1) * 128, h = (bid >> 1) & 255, b = bid >> 9;
    int tid = threadIdx.x;
    int ox = tid & 7;
    int py = tid >> 3;
    int lane = tid & 31, wbase = tid & 96, sub = lane >> 3, lane8 = lane & 7;
    int rowpix = (b * HH + h) * WW + w0;

    unsigned long long acc[4][8];
#pragma unroll
    for (int i = 0; i < 4; i++)
#pragma unroll
        for (int j = 0; j < 8; j++) acc[i][j] = 0ull;

    // ---------- plain-conv branch: taps t = 9..17, cooperative coalesced copy ----------
#pragma unroll 1
    for (int n = 0; n < 9; n++) {
        int kh = n / 3 - 1, kw = n % 3 - 1;
        km_load_W(9 + n, Wsh, tid);
        const float* srow = g_xp + ((b * HPAD + h + 1 + kh) * WPAD + (w0 + 1 + kw)) * CC;
        fill_plain(Ssh, srow, wbase, sub, lane8);
        __syncthreads();
        km_mma(Ssh, Wsh, acc, py, ox);
        __syncthreads();
    }

    // ---------- deform branches: cooperative coalesced bilinear gather ----------
#pragma unroll 1
    for (int half = 0; half < 2; half++) {
        int ob = half * 18;
#pragma unroll 1
        for (int n = 0; n < 9; n++) {
            int kh = n / 3 - 1, kw = n % 3 - 1;
            km_load_W(ob + n, Wsh, tid);
            const float* offpx = g_off + (size_t)(ob + n) * NPIX + rowpix;
            const float* offpy = g_off + (size_t)(ob + 9 + n) * NPIX + rowpix;
#pragma unroll 1
            for (int g = 0; g < 8; g++) {
                int pp = wbase + g * 4 + sub;
                // 8-way-broadcast offset loads (1 line/warp) + per-lane bilinear recompute
                float offx = offpx[pp];
                float offy = offpy[pp];
                float pxf = offx + (float)(h + 1 + kh);
                float pyf = offy + (float)(w0 + pp + 1 + kw);
                float fx = floorf(pxf), fy = floorf(pyf);
                float qltx = fminf(fmaxf(fx, 0.f), 257.f);
                float qlty = fminf(fmaxf(fy, 0.f), 257.f);
                float qrbx = fminf(fmaxf(fx + 1.f, 0.f), 257.f);
                float qrby = fminf(fmaxf(fy + 1.f, 0.f), 257.f);
                float pxc = fminf(fmaxf(pxf, 0.f), 257.f);
                float pyc = fminf(fmaxf(pyf, 0.f), 257.f);
                float gxl = 1.f + (qltx - pxc), gyl = 1.f + (qlty - pyc);
                float gxr = 1.f - (qrbx - pxc), gyr = 1.f - (qrby - pyc);
                float glt = gxl * gyl, grb = gxr * gyr, glb = gxl * gyr, grt = gxr * gyl;
                int ilx = (int)qltx, ily = (int)qlty, irx = (int)qrbx, iry = (int)qrby;
                int rowL = (b * HPAD + ilx) * WPAD;
                int rowR = (b * HPAD + irx) * WPAD;
                const float4* pA = reinterpret_cast<const float4*>(g_xp + (rowL + ily) * CC);
                const float4* pB = reinterpret_cast<const float4*>(g_xp + (rowR + iry) * CC);
                const float4* pC = reinterpret_cast<const float4*>(g_xp + (rowL + iry) * CC);
                const float4* pD = reinterpret_cast<const float4*>(g_xp + (rowR + ily) * CC);
                int col = pp ^ (lane8 << 2);
#pragma unroll
                for (int t2 = 0; t2 < 2; t2++) {
                    int c4 = lane8 + t2 * 8;
                    float4 a = pA[c4], bb2 = pB[c4], cv = pC[c4], dv = pD[c4];
                    float4 v;
                    v.x = glt * a.x + grb * bb2.x + glb * cv.x + grt * dv.x;
                    v.y = glt * a.y + grb * bb2.y + glb * cv.y + grt * dv.y;
                    v.z = glt * a.z + grb * bb2.z + glb * cv.z + grt * dv.z;
                    v.w = glt * a.w + grb * bb2.w + glb * cv.w + grt * dv.w;
                    Ssh[4 * c4 + 0][col] = v.x;
                    Ssh[4 * c4 + 1][col] = v.y;
                    Ssh[4 * c4 + 2][col] = v.z;
                    Ssh[4 * c4 + 3][col] = v.w;
                }
            }
            __syncthreads();
            km_mma(Ssh, Wsh, acc, py, ox);
            __syncthreads();
        }
    }

    // epilogue: bias + residual, NCHW output
    int pxb = py * 8;
#pragma unroll
    for (int j = 0; j < 8; j++) {
        int oc = (j < 4) ? (ox * 4 + j) : (32 + ox * 4 + (j - 4));
        float bsum = g_bias[oc];
        size_t base = ((size_t)((b * CC + oc) * HH + h)) * WW + w0 + pxb;
        float4 r0 = *reinterpret_cast<const float4*>(&x[base]);
        float4 r1 = *reinterpret_cast<const float4*>(&x[base + 4]);
        float4 o0, o1;
        o0.x = lo32(acc[0][j]) + bsum + r0.x;
        o0.y = hi32(acc[0][j]) + bsum + r0.y;
        o0.z = lo32(acc[1][j]) + bsum + r0.z;
        o0.w = hi32(acc[1][j]) + bsum + r0.w;
        o1.x = lo32(acc[2][j]) + bsum + r1.x;
        o1.y = hi32(acc[2][j]) + bsum + r1.y;
        o1.z = lo32(acc[3][j]) + bsum + r1.z;
        o1.w = hi32(acc[3][j]) + bsum + r1.w;
        *reinterpret_cast<float4*>(&out[base]) = o0;
        *reinterpret_cast<float4*>(&out[base + 4]) = o1;
    }
}

extern "C" void kernel_launch(void* const* d_in, const int* in_sizes, int n_in,
                              void* d_out, int out_size) {
    const float* x    = (const float*)d_in[0];
    const float* wp_x = (const float*)d_in[1];
    const float* bp_x = (const float*)d_in[2];
    const float* wc_x = (const float*)d_in[3];
    const float* wm   = (const float*)d_in[4];
    const float* bm   = (const float*)d_in[5];
    const float* wp_y = (const float*)d_in[6];
    const float* bp_y = (const float*)d_in[7];
    const float* wc_y = (const float*)d_in[8];
    const float* wo   = (const float*)d_in[9];
    const float* bo   = (const float*)d_in[10];
    float* out = (float*)d_out;

    k_prep<<<(PREP_TOTAL + 255) / 256, 256>>>(wo, wc_x, wm, wc_y, wp_x, wp_y, bo, bm);
    k_transpose<<<BB * HH * (WW / 64), 256>>>(x);
    k_offsets<<<BB * HH * (WW / 128), 128>>>(bp_x, bp_y);
    k_main<<<BB * HH * (WW / 128), 128>>>(x, out);
}